// round 1
// baseline (speedup 1.0000x reference)
#include <cuda_runtime.h>
#include <cuda_bf16.h>

// Problem constants
#define R_REL 8
#define C_CH  4
#define E_EDG 2000000LL
#define RE    (R_REL * E_EDG)          // 16,000,000

__device__ float g_filt[R_REL * C_CH]; // softmax(weight, axis=0), row-major [R][C]
__device__ int   g_is64;               // 1 if edge_index is int64, 0 if int32

// ---------------------------------------------------------------------------
// Softmax over relations (dim 0) for each of the 4 channels. 32 floats total.
// ---------------------------------------------------------------------------
__global__ void softmax_kernel(const float* __restrict__ w) {
    int c = threadIdx.x;
    if (c < C_CH) {
        float v[R_REL];
        float m = -1e30f;
        #pragma unroll
        for (int r = 0; r < R_REL; r++) {
            v[r] = w[r * C_CH + c];
            m = fmaxf(m, v[r]);
        }
        float s = 0.f;
        #pragma unroll
        for (int r = 0; r < R_REL; r++) {
            v[r] = expf(v[r] - m);
            s += v[r];
        }
        float inv = 1.f / s;
        #pragma unroll
        for (int r = 0; r < R_REL; r++)
            g_filt[r * C_CH + c] = v[r] * inv;
    }
}

// ---------------------------------------------------------------------------
// Detect whether edge_index arrived as int64 or int32 (jax x64-flag unknown).
// Node ids are in [0, 100000) so genuine int64 data has ALL high-32 bits zero.
// int32 data reinterpreted as qwords puts the next id in the high word; the
// chance all 16 high words are zero is (1e-5)^16 ~= 0.
// ---------------------------------------------------------------------------
__global__ void detect_kernel(const unsigned long long* __restrict__ ei) {
    if (threadIdx.x == 0) {
        int is64 = 1;
        #pragma unroll
        for (int i = 0; i < 16; i++)
            if ((ei[i] >> 32) != 0ULL) is64 = 0;
        g_is64 = is64;
    }
}

// ---------------------------------------------------------------------------
// Main streaming kernel. One thread = 4 consecutive edges of one relation.
// Output layout (float32):
//   [0*RE .. 1*RE)  : edge_index[r, 0, e]  at slot r*E+e
//   [1*RE .. 2*RE)  : edge_index[r, 1, e]
//   [2*RE + c*RE)   : filt[r][c] * edge_value[r, e],  c = 0..3
// ---------------------------------------------------------------------------
__global__ void __launch_bounds__(256) gtconv_kernel(
    const void* __restrict__ edge_index_raw,
    const float* __restrict__ edge_value,
    float* __restrict__ out)
{
    const long long CHUNKS_PER_R = E_EDG / 4;                 // 500,000
    long long tid = (long long)blockIdx.x * blockDim.x + threadIdx.x;
    if (tid >= (long long)R_REL * CHUNKS_PER_R) return;

    int       r = (int)(tid / CHUNKS_PER_R);
    long long e = (tid % CHUNKS_PER_R) * 4;

    // per-relation softmax coefficients (16B aligned)
    const float4 f = *reinterpret_cast<const float4*>(&g_filt[r * C_CH]);

    float4 o0, o1;
    if (g_is64) {
        const long long* ei = (const long long*)edge_index_raw;
        const longlong2* p0 = reinterpret_cast<const longlong2*>(ei + (long long)r * 2 * E_EDG + e);
        const longlong2* p1 = reinterpret_cast<const longlong2*>(ei + (long long)r * 2 * E_EDG + E_EDG + e);
        longlong2 a = p0[0], b = p0[1];
        longlong2 c2 = p1[0], d2 = p1[1];
        o0 = make_float4((float)(int)a.x,  (float)(int)a.y,  (float)(int)b.x,  (float)(int)b.y);
        o1 = make_float4((float)(int)c2.x, (float)(int)c2.y, (float)(int)d2.x, (float)(int)d2.y);
    } else {
        const int* ei = (const int*)edge_index_raw;
        int4 a = *reinterpret_cast<const int4*>(ei + (long long)r * 2 * E_EDG + e);
        int4 b = *reinterpret_cast<const int4*>(ei + (long long)r * 2 * E_EDG + E_EDG + e);
        o0 = make_float4((float)a.x, (float)a.y, (float)a.z, (float)a.w);
        o1 = make_float4((float)b.x, (float)b.y, (float)b.z, (float)b.w);
    }

    long long base = (long long)r * E_EDG + e;
    *reinterpret_cast<float4*>(out + base)      = o0;
    *reinterpret_cast<float4*>(out + RE + base) = o1;

    float4 v = *reinterpret_cast<const float4*>(edge_value + base);
    float* vbase = out + 2 * RE + base;
    *reinterpret_cast<float4*>(vbase + 0 * RE) = make_float4(v.x * f.x, v.y * f.x, v.z * f.x, v.w * f.x);
    *reinterpret_cast<float4*>(vbase + 1 * RE) = make_float4(v.x * f.y, v.y * f.y, v.z * f.y, v.w * f.y);
    *reinterpret_cast<float4*>(vbase + 2 * RE) = make_float4(v.x * f.z, v.y * f.z, v.z * f.z, v.w * f.z);
    *reinterpret_cast<float4*>(vbase + 3 * RE) = make_float4(v.x * f.w, v.y * f.w, v.z * f.w, v.w * f.w);
}

extern "C" void kernel_launch(void* const* d_in, const int* in_sizes, int n_in,
                              void* d_out, int out_size) {
    const float* weight     = (const float*)d_in[0];
    const void*  edge_index = (const void*)d_in[1];
    const float* edge_value = (const float*)d_in[2];
    float* out = (float*)d_out;

    softmax_kernel<<<1, 32>>>(weight);
    detect_kernel<<<1, 32>>>((const unsigned long long*)edge_index);

    const long long total_chunks = (long long)R_REL * (E_EDG / 4); // 4,000,000
    int threads = 256;
    int blocks  = (int)((total_chunks + threads - 1) / threads);   // 15,625
    gtconv_kernel<<<blocks, threads>>>(edge_index, edge_value, out);
}

// round 5
// speedup vs baseline: 1.0495x; 1.0495x over previous
#include <cuda_runtime.h>
#include <cuda_bf16.h>

// Problem constants
#define R_REL 8
#define C_CH  4
#define E_EDG 2000000LL
#define RE    (R_REL * E_EDG)          // 16,000,000

// ---------------------------------------------------------------------------
// Single fused kernel.
//  - warp 0, lanes 0-3: compute softmax(weight, axis=0) into smem (redundant
//    per block; weight is 32 floats, hits L2, trivially overlapped).
//  - warp 1, lane 0: detect int64 vs int32 edge_index (node ids < 1e5, so
//    genuine int64 data has all high-32 bits zero; 16 probes -> P(err)~1e-80).
//  - all threads: stream 4 edges each.
// Output layout (float32):
//   [0*RE .. 1*RE)  : (float)edge_index[r, 0, e]  at slot r*E+e
//   [1*RE .. 2*RE)  : (float)edge_index[r, 1, e]
//   [2*RE + c*RE)   : filt[r][c] * edge_value[r, e],  c = 0..3
// ---------------------------------------------------------------------------
__global__ void __launch_bounds__(256) gtconv_fused_kernel(
    const float* __restrict__ weight,
    const void*  __restrict__ edge_index_raw,
    const float* __restrict__ edge_value,
    float* __restrict__ out)
{
    __shared__ float s_filt[R_REL * C_CH];
    __shared__ int   s_is64;

    int t = threadIdx.x;
    if (t < C_CH) {
        // softmax over relations for channel t
        float v[R_REL];
        float m = -1e30f;
        #pragma unroll
        for (int r = 0; r < R_REL; r++) {
            v[r] = __ldg(&weight[r * C_CH + t]);
            m = fmaxf(m, v[r]);
        }
        float s = 0.f;
        #pragma unroll
        for (int r = 0; r < R_REL; r++) {
            v[r] = __expf(v[r] - m);
            s += v[r];
        }
        float inv = 1.f / s;
        #pragma unroll
        for (int r = 0; r < R_REL; r++)
            s_filt[r * C_CH + t] = v[r] * inv;
    } else if (t == 32) {
        const unsigned long long* q = (const unsigned long long*)edge_index_raw;
        int is64 = 1;
        #pragma unroll
        for (int i = 0; i < 16; i++)
            if ((__ldg(&q[i]) >> 32) != 0ULL) is64 = 0;
        s_is64 = is64;
    }
    __syncthreads();

    const long long CHUNKS_PER_R = E_EDG / 4;                 // 500,000
    long long tid = (long long)blockIdx.x * blockDim.x + t;   // exact cover: 4,000,000

    int       r = (int)(tid / CHUNKS_PER_R);
    long long e = (tid % CHUNKS_PER_R) * 4;

    // per-relation softmax coefficients (broadcast LDS, no conflicts)
    const float4 f = *reinterpret_cast<const float4*>(&s_filt[r * C_CH]);

    float4 o0, o1;
    if (s_is64) {
        const long long* ei = (const long long*)edge_index_raw;
        const longlong2* p0 = reinterpret_cast<const longlong2*>(ei + (long long)r * 2 * E_EDG + e);
        const longlong2* p1 = reinterpret_cast<const longlong2*>(ei + (long long)r * 2 * E_EDG + E_EDG + e);
        longlong2 a  = __ldcs(&p0[0]);
        longlong2 b  = __ldcs(&p0[1]);
        longlong2 c2 = __ldcs(&p1[0]);
        longlong2 d2 = __ldcs(&p1[1]);
        o0 = make_float4((float)(int)a.x,  (float)(int)a.y,  (float)(int)b.x,  (float)(int)b.y);
        o1 = make_float4((float)(int)c2.x, (float)(int)c2.y, (float)(int)d2.x, (float)(int)d2.y);
    } else {
        const int* ei = (const int*)edge_index_raw;
        int4 a = __ldcs(reinterpret_cast<const int4*>(ei + (long long)r * 2 * E_EDG + e));
        int4 b = __ldcs(reinterpret_cast<const int4*>(ei + (long long)r * 2 * E_EDG + E_EDG + e));
        o0 = make_float4((float)a.x, (float)a.y, (float)a.z, (float)a.w);
        o1 = make_float4((float)b.x, (float)b.y, (float)b.z, (float)b.w);
    }

    long long base = (long long)r * E_EDG + e;
    __stcs(reinterpret_cast<float4*>(out + base),      o0);
    __stcs(reinterpret_cast<float4*>(out + RE + base), o1);

    float4 v = __ldcs(reinterpret_cast<const float4*>(edge_value + base));
    float* vbase = out + 2 * RE + base;
    __stcs(reinterpret_cast<float4*>(vbase + 0 * RE),
           make_float4(v.x * f.x, v.y * f.x, v.z * f.x, v.w * f.x));
    __stcs(reinterpret_cast<float4*>(vbase + 1 * RE),
           make_float4(v.x * f.y, v.y * f.y, v.z * f.y, v.w * f.y));
    __stcs(reinterpret_cast<float4*>(vbase + 2 * RE),
           make_float4(v.x * f.z, v.y * f.z, v.z * f.z, v.w * f.z));
    __stcs(reinterpret_cast<float4*>(vbase + 3 * RE),
           make_float4(v.x * f.w, v.y * f.w, v.z * f.w, v.w * f.w));
}

extern "C" void kernel_launch(void* const* d_in, const int* in_sizes, int n_in,
                              void* d_out, int out_size) {
    const float* weight     = (const float*)d_in[0];
    const void*  edge_index = (const void*)d_in[1];
    const float* edge_value = (const float*)d_in[2];
    float* out = (float*)d_out;

    const long long total_chunks = (long long)R_REL * (E_EDG / 4); // 4,000,000
    int threads = 256;
    int blocks  = (int)(total_chunks / threads);                   // 15,625 exact
    gtconv_fused_kernel<<<blocks, threads>>>(weight, edge_index, edge_value, out);
}